// round 5
// baseline (speedup 1.0000x reference)
#include <cuda_runtime.h>
#include <cuda_bf16.h>
#include <cuda_fp8.h>
#include <cstdint>

// SOM layer: coarse fp8(e4m3) mma.sync GEMM (scores + candidate capture) then
// exact fp32 refinement of candidates -> argmin identical to reference.
// R5: m16n8k32 e4m3 doubles MACs/instruction vs bf16 k16 (SIMT HMMA pipe
// measured at ~512 MAC/cyc/SM = the R3/R4 wall). Margin widened for fp8 error.

#define DDIM 512
#define MAXN 32768
#define MAXM 4096
#define CAND_CAP 64
#define COARSE_THR 16.0f   // ~7 sigma of fp8 coarse-score error (sigma~2.3)

#define BM 256
#define BN 128
#define BK 64              // fp8 elements per k-tile = 64 bytes/row
#define NTHREADS 256       // 8 warps: 4(m) x 2(n), warp tile 64x64
#define STAGES 4
#define A_STAGE_BYTES (BM * 64)            // 16384
#define B_STAGE_BYTES (BN * 64)            // 8192
#define STAGE_BYTES (A_STAGE_BYTES + B_STAGE_BYTES)  // 24576
#define SMEM_BYTES (STAGES * STAGE_BYTES)  // 98304

// ---------------- device global scratch (allocation-free rule) --------------
__device__ float g_p2[MAXM];
__device__ float g_z2[MAXN];
__device__ __align__(128) uint8_t g_zq[MAXN * DDIM];   // 16MB e4m3
__device__ __align__(128) uint8_t g_pq[MAXM * DDIM];   // 2MB  e4m3
__device__ float    g_cval[(size_t)MAXN * CAND_CAP];
__device__ int      g_cidx[(size_t)MAXN * CAND_CAP];
__device__ int      g_ccnt[MAXN];
__device__ unsigned g_best[MAXN];

// ---------------- helpers ----------------------------------------------------
__device__ __forceinline__ uint32_t smem_u32(const void* p) {
    uint32_t a;
    asm("{ .reg .u64 t; cvta.to.shared.u64 t, %1; cvt.u32.u64 %0, t; }"
        : "=r"(a) : "l"(p));
    return a;
}
__device__ __forceinline__ void cp16(uint32_t dst, const void* src) {
    asm volatile("cp.async.cg.shared.global [%0], [%1], 16;" :: "r"(dst), "l"(src));
}
__device__ __forceinline__ void mma_fp8(float* c, const uint32_t* a,
                                        uint32_t b0, uint32_t b1) {
    asm volatile(
        "mma.sync.aligned.m16n8k32.row.col.f32.e4m3.e4m3.f32 "
        "{%0,%1,%2,%3}, {%4,%5,%6,%7}, {%8,%9}, {%0,%1,%2,%3};"
        : "+f"(c[0]), "+f"(c[1]), "+f"(c[2]), "+f"(c[3])
        : "r"(a[0]), "r"(a[1]), "r"(a[2]), "r"(a[3]), "r"(b0), "r"(b1));
}
#define LDSM4(r0, r1, r2, r3, addr) \
    asm volatile("ldmatrix.sync.aligned.m8n8.x4.shared.b16 {%0,%1,%2,%3}, [%4];" \
                 : "=r"(r0), "=r"(r1), "=r"(r2), "=r"(r3) : "r"(addr))

// ---------------- init / fused sum-of-squares + fp8 convert ------------------
__global__ void zero_kernel(int n) {
    int i = blockIdx.x * blockDim.x + threadIdx.x;
    if (i < n) { g_ccnt[i] = 0; g_best[i] = 0x7F800000u; }
}

__device__ __forceinline__ uint32_t pack4_e4m3(float4 v) {
    __nv_fp8x2_storage_t lo = __nv_cvt_float2_to_fp8x2(make_float2(v.x, v.y),
                                                       __NV_SATFINITE, __NV_E4M3);
    __nv_fp8x2_storage_t hi = __nv_cvt_float2_to_fp8x2(make_float2(v.z, v.w),
                                                       __NV_SATFINITE, __NV_E4M3);
    return (uint32_t)lo | ((uint32_t)hi << 16);
}

// one warp per row: exact fp32 sum-of-squares + e4m3 conversion (single read)
__global__ void sqcvt_kernel(const float* __restrict__ x, float* __restrict__ sq,
                             uint8_t* __restrict__ q, int rows) {
    int warp = (blockIdx.x * blockDim.x + threadIdx.x) >> 5;
    int lane = threadIdx.x & 31;
    if (warp >= rows) return;
    const float4* xr = reinterpret_cast<const float4*>(x) + (size_t)warp * (DDIM / 4);
    float4 v[4];
    float s = 0.f;
#pragma unroll
    for (int i = 0; i < 4; i++) {
        v[i] = xr[lane * 4 + i];
        s += v[i].x * v[i].x + v[i].y * v[i].y + v[i].z * v[i].z + v[i].w * v[i].w;
    }
    uint4 u;
    u.x = pack4_e4m3(v[0]); u.y = pack4_e4m3(v[1]);
    u.z = pack4_e4m3(v[2]); u.w = pack4_e4m3(v[3]);
    *reinterpret_cast<uint4*>(q + (size_t)warp * DDIM + lane * 16) = u;
#pragma unroll
    for (int o = 16; o; o >>= 1) s += __shfl_xor_sync(0xffffffffu, s, o);
    if (lane == 0) sq[warp] = s;
}

// ---------------- main coarse GEMM + candidate capture ----------------------
// smem per stage: A (256 rows x 64B, XOR-swizzled chunks) then B (128 x 64B).
// chunk address: row*64 + ((chunk ^ ((row>>1)&3)) * 16)  -- identical to R4;
// ldmatrix b16 is content-agnostic, fragment map matches m16n8k32 e4m3.
__global__ __launch_bounds__(NTHREADS, 1)
void som_mma_kernel() {
    extern __shared__ __align__(128) unsigned char smem[];
    __shared__ unsigned srow[BM];

    const int tid = threadIdx.x;
    const int wid = tid >> 5;
    const int lane = tid & 31;
    const int wm = wid >> 1;          // 0..3
    const int wn = wid & 1;           // 0..1
    const int m8 = lane >> 3;         // ldmatrix matrix id 0..3
    const int r8 = lane & 7;
    const int crow = lane >> 2;       // mma C row within 8
    const int qc = lane & 3;

    const int rowBase = blockIdx.x * BM;
    const int colBase = blockIdx.y * BN;

    const uint8_t* gA = g_zq + (size_t)rowBase * DDIM;
    const uint8_t* gB = g_pq + (size_t)colBase * DDIM;

    const uint32_t sbase = smem_u32(smem);

    if (tid < BM) srow[tid] = 0xFFFFFFFFu;

    // per-lane ldmatrix offsets (stage-relative); kf selects 32B k-half
    uint32_t aOff[2][4], bOff[2][4];
    {
        int rowW = wm * 64 + (m8 & 1) * 8 + r8;
        int sxa = (rowW >> 1) & 3;
#pragma unroll
        for (int kf = 0; kf < 2; kf++)
#pragma unroll
            for (int mi = 0; mi < 4; mi++)
                aOff[kf][mi] = (uint32_t)((rowW + mi * 16) * 64 +
                               (((kf * 2 + (m8 >> 1)) ^ sxa) << 4));
        int nW = wn * 64 + (m8 >> 1) * 8 + r8;
        int sxb = (nW >> 1) & 3;
#pragma unroll
        for (int kf = 0; kf < 2; kf++)
#pragma unroll
            for (int p = 0; p < 4; p++)
                bOff[kf][p] = (uint32_t)(A_STAGE_BYTES + (nW + p * 16) * 64 +
                              (((kf * 2 + (m8 & 1)) ^ sxb) << 4));
    }

    float acc[4][8][4];
#pragma unroll
    for (int mi = 0; mi < 4; mi++)
#pragma unroll
        for (int ni = 0; ni < 8; ni++)
#pragma unroll
            for (int c = 0; c < 4; c++) acc[mi][ni][c] = 0.f;

    const int KT = DDIM / BK;  // 8

    auto loadStage = [&](int st, int kt) {
        const uint32_t base = sbase + st * STAGE_BYTES;
#pragma unroll
        for (int i = 0; i < 4; i++) {         // A: 1024 16B chunks
            int id = tid + i * NTHREADS;
            int r = id >> 2, c = id & 3;
            cp16(base + r * 64 + (((c ^ ((r >> 1) & 3))) << 4),
                 gA + (size_t)r * DDIM + kt * BK + c * 16);
        }
#pragma unroll
        for (int i = 0; i < 2; i++) {         // B: 512 16B chunks
            int id = tid + i * NTHREADS;
            int r = id >> 2, c = id & 3;
            cp16(base + A_STAGE_BYTES + r * 64 + (((c ^ ((r >> 1) & 3))) << 4),
                 gB + (size_t)r * DDIM + kt * BK + c * 16);
        }
        asm volatile("cp.async.commit_group;");
    };

    loadStage(0, 0);
    loadStage(1, 1);
    loadStage(2, 2);

    for (int kt = 0; kt < KT; kt++) {
        asm volatile("cp.async.wait_group 2;");
        __syncthreads();
        if (kt + 3 < KT) loadStage((kt + 3) & 3, kt + 3);

        const uint32_t stg = sbase + (kt & 3) * STAGE_BYTES;
#pragma unroll
        for (int kf = 0; kf < 2; kf++) {       // each kf = one k32 mma step
            uint32_t a[4][4];
#pragma unroll
            for (int mi = 0; mi < 4; mi++)
                LDSM4(a[mi][0], a[mi][1], a[mi][2], a[mi][3], stg + aOff[kf][mi]);
#pragma unroll
            for (int p = 0; p < 4; p++) {
                uint32_t b0, b1, b2, b3;
                LDSM4(b0, b1, b2, b3, stg + bOff[kf][p]);
#pragma unroll
                for (int mi = 0; mi < 4; mi++) {
                    mma_fp8(acc[mi][2 * p],     a[mi], b0, b1);
                    mma_fp8(acc[mi][2 * p + 1], a[mi], b2, b3);
                }
            }
        }
        __syncthreads();
    }

    // ---- epilogue: d = z2 - 2*dot + p2, per-row min, candidate append -------
#pragma unroll
    for (int mi = 0; mi < 4; mi++) {
#pragma unroll
        for (int h = 0; h < 2; h++) {
            int lrow = wm * 64 + mi * 16 + crow + h * 8;
            float z2v = g_z2[rowBase + lrow];
            float tmin = 3.4e38f;
#pragma unroll
            for (int ni = 0; ni < 8; ni++) {
                int gcol = colBase + wn * 64 + ni * 8 + 2 * qc;
                float d0 = (z2v - 2.0f * acc[mi][ni][2 * h])     + __ldg(&g_p2[gcol]);
                float d1 = (z2v - 2.0f * acc[mi][ni][2 * h + 1]) + __ldg(&g_p2[gcol + 1]);
                acc[mi][ni][2 * h] = d0;
                acc[mi][ni][2 * h + 1] = d1;
                tmin = fminf(tmin, fminf(d0, d1));
            }
            atomicMin(&srow[lrow], __float_as_uint(tmin));
        }
    }
    __syncthreads();

    if (tid < BM) atomicMin(&g_best[rowBase + tid], srow[tid]);

#pragma unroll
    for (int mi = 0; mi < 4; mi++) {
#pragma unroll
        for (int h = 0; h < 2; h++) {
            int lrow = wm * 64 + mi * 16 + crow + h * 8;
            int grow = rowBase + lrow;
            float gb = fminf(__uint_as_float(g_best[grow]),
                             __uint_as_float(srow[lrow]));
            float thr = gb + COARSE_THR;
#pragma unroll
            for (int ni = 0; ni < 8; ni++) {
                int gcol = colBase + wn * 64 + ni * 8 + 2 * qc;
#pragma unroll
                for (int e = 0; e < 2; e++) {
                    float d = acc[mi][ni][2 * h + e];
                    if (d < thr) {
                        int slot = atomicAdd(&g_ccnt[grow], 1);
                        if (slot < CAND_CAP) {
                            g_cval[(size_t)grow * CAND_CAP + slot] = d;
                            g_cidx[(size_t)grow * CAND_CAP + slot] = gcol + e;
                        }
                    }
                }
            }
        }
    }
}

// ---------------- exact refinement + output ---------------------------------
__global__ void refine_kernel(const float* __restrict__ z,
                              const float* __restrict__ proto, int Mtot,
                              float* __restrict__ outW,
                              float* __restrict__ outIdxF,
                              int* __restrict__ outIdxI) {
    int warp = (blockIdx.x * blockDim.x + threadIdx.x) >> 5;
    int lane = threadIdx.x & 31;
    const int row = warp;
    const float z2 = g_z2[row];

    float4 zr[4];
#pragma unroll
    for (int i = 0; i < 4; i++)
        zr[i] = reinterpret_cast<const float4*>(z + (size_t)row * DDIM)[i * 32 + lane];

    int cnt = g_ccnt[row];
    float bestD = 3.4e38f;
    int bestI = 0;

    if (cnt <= CAND_CAP) {
        for (int k = 0; k < cnt; k++) {
            int c = g_cidx[(size_t)row * CAND_CAP + k];
            const float4* pr = reinterpret_cast<const float4*>(proto + (size_t)c * DDIM);
            float dot = 0.f;
#pragma unroll
            for (int i = 0; i < 4; i++) {
                float4 pv = pr[i * 32 + lane];
                dot += zr[i].x * pv.x + zr[i].y * pv.y + zr[i].z * pv.z + zr[i].w * pv.w;
            }
#pragma unroll
            for (int o = 16; o; o >>= 1) dot += __shfl_xor_sync(0xffffffffu, dot, o);
            float d = (z2 - 2.0f * dot) + __ldg(&g_p2[c]);
            if (d < bestD || (d == bestD && c < bestI)) { bestD = d; bestI = c; }
        }
    } else {
        for (int c = 0; c < Mtot; c++) {
            const float4* pr = reinterpret_cast<const float4*>(proto + (size_t)c * DDIM);
            float dot = 0.f;
#pragma unroll
            for (int i = 0; i < 4; i++) {
                float4 pv = pr[i * 32 + lane];
                dot += zr[i].x * pv.x + zr[i].y * pv.y + zr[i].z * pv.z + zr[i].w * pv.w;
            }
#pragma unroll
            for (int o = 16; o; o >>= 1) dot += __shfl_xor_sync(0xffffffffu, dot, o);
            float d = (z2 - 2.0f * dot) + __ldg(&g_p2[c]);
            if (d < bestD) { bestD = d; bestI = c; }
        }
    }

    if (lane == 0) {
        if (outIdxF) outIdxF[row] = (float)bestI;
        if (outIdxI) outIdxI[row] = bestI;
    }
    if (outW) {
        const float4* pr = reinterpret_cast<const float4*>(proto + (size_t)bestI * DDIM);
        float4* ow = reinterpret_cast<float4*>(outW + (size_t)row * DDIM);
#pragma unroll
        for (int i = 0; i < 4; i++) ow[i * 32 + lane] = pr[i * 32 + lane];
    }
}

// ---------------------------------------------------------------------------
extern "C" void kernel_launch(void* const* d_in, const int* in_sizes, int n_in,
                              void* d_out, int out_size) {
    const float* z = (const float*)d_in[0];
    const float* p = (const float*)d_in[1];
    int N = in_sizes[0] / DDIM;
    int M = in_sizes[1] / DDIM;

    float* p2; float* z2; uint8_t* zq; uint8_t* pq;
    cudaGetSymbolAddress((void**)&p2, g_p2);
    cudaGetSymbolAddress((void**)&z2, g_z2);
    cudaGetSymbolAddress((void**)&zq, g_zq);
    cudaGetSymbolAddress((void**)&pq, g_pq);

    zero_kernel<<<(N + 255) / 256, 256>>>(N);
    sqcvt_kernel<<<(M * 32 + 255) / 256, 256>>>(p, p2, pq, M);
    sqcvt_kernel<<<(N * 32 + 255) / 256, 256>>>(z, z2, zq, N);

    cudaFuncSetAttribute(som_mma_kernel,
                         cudaFuncAttributeMaxDynamicSharedMemorySize, SMEM_BYTES);
    dim3 grid(N / BM, M / BN);   // x = row tiles (fast), y = col tiles
    som_mma_kernel<<<grid, NTHREADS, SMEM_BYTES>>>();

    float* outW = nullptr;
    float* outIdxF = nullptr;
    int* outIdxI = nullptr;
    long long nd = (long long)N * DDIM;
    if ((long long)out_size >= nd) {
        outW = (float*)d_out;
        if ((long long)out_size >= nd + N) outIdxF = (float*)d_out + nd;
    } else if (out_size == N) {
        outIdxI = (int*)d_out;
    }

    refine_kernel<<<(N * 32) / 256, 256>>>(z, p, M, outW, outIdxF, outIdxI);
}

// round 6
// speedup vs baseline: 1.3970x; 1.3970x over previous
#include <cuda_runtime.h>
#include <cuda_bf16.h>
#include <cuda_fp8.h>
#include <cstdint>

// SOM layer: coarse fp8(e4m3) mma.sync GEMM (scores + candidate capture) then
// exact fp32 refinement of candidates -> argmin identical to reference.
// R6: occupancy-first restructure. R5 profile showed tensor=35%, occ=12%,
// regs=255 (spilling) -> latency-bound. Warp tile 64x32 (acc=64 regs),
// launch_bounds(256,2) -> 2 CTA/SM, 16 warps.

#define DDIM 512
#define MAXN 32768
#define MAXM 4096
#define CAND_CAP 64
#define COARSE_THR 16.0f   // ~7 sigma of fp8 coarse-score error

#define BM 128
#define BN 128
#define BK 64              // fp8 elements per k-tile = 64 bytes/row
#define NTHREADS 256       // 8 warps: 2(m) x 4(n), warp tile 64x32
#define STAGES 4
#define A_STAGE_BYTES (BM * 64)            // 8192
#define B_STAGE_BYTES (BN * 64)            // 8192
#define STAGE_BYTES (A_STAGE_BYTES + B_STAGE_BYTES)  // 16384
#define SMEM_BYTES (STAGES * STAGE_BYTES)  // 65536

// ---------------- device global scratch (allocation-free rule) --------------
__device__ float g_p2[MAXM];
__device__ float g_z2[MAXN];
__device__ __align__(128) uint8_t g_zq[MAXN * DDIM];   // 16MB e4m3
__device__ __align__(128) uint8_t g_pq[MAXM * DDIM];   // 2MB  e4m3
__device__ float    g_cval[(size_t)MAXN * CAND_CAP];
__device__ int      g_cidx[(size_t)MAXN * CAND_CAP];
__device__ int      g_ccnt[MAXN];
__device__ unsigned g_best[MAXN];

// ---------------- helpers ----------------------------------------------------
__device__ __forceinline__ uint32_t smem_u32(const void* p) {
    uint32_t a;
    asm("{ .reg .u64 t; cvta.to.shared.u64 t, %1; cvt.u32.u64 %0, t; }"
        : "=r"(a) : "l"(p));
    return a;
}
__device__ __forceinline__ void cp16(uint32_t dst, const void* src) {
    asm volatile("cp.async.cg.shared.global [%0], [%1], 16;" :: "r"(dst), "l"(src));
}
__device__ __forceinline__ void mma_fp8(float* c, const uint32_t* a,
                                        uint32_t b0, uint32_t b1) {
    asm volatile(
        "mma.sync.aligned.m16n8k32.row.col.f32.e4m3.e4m3.f32 "
        "{%0,%1,%2,%3}, {%4,%5,%6,%7}, {%8,%9}, {%0,%1,%2,%3};"
        : "+f"(c[0]), "+f"(c[1]), "+f"(c[2]), "+f"(c[3])
        : "r"(a[0]), "r"(a[1]), "r"(a[2]), "r"(a[3]), "r"(b0), "r"(b1));
}
#define LDSM4(r0, r1, r2, r3, addr) \
    asm volatile("ldmatrix.sync.aligned.m8n8.x4.shared.b16 {%0,%1,%2,%3}, [%4];" \
                 : "=r"(r0), "=r"(r1), "=r"(r2), "=r"(r3) : "r"(addr))

// ---------------- init / fused sum-of-squares + fp8 convert ------------------
__global__ void zero_kernel(int n) {
    int i = blockIdx.x * blockDim.x + threadIdx.x;
    if (i < n) { g_ccnt[i] = 0; g_best[i] = 0x7F800000u; }
}

__device__ __forceinline__ uint32_t pack4_e4m3(float4 v) {
    __nv_fp8x2_storage_t lo = __nv_cvt_float2_to_fp8x2(make_float2(v.x, v.y),
                                                       __NV_SATFINITE, __NV_E4M3);
    __nv_fp8x2_storage_t hi = __nv_cvt_float2_to_fp8x2(make_float2(v.z, v.w),
                                                       __NV_SATFINITE, __NV_E4M3);
    return (uint32_t)lo | ((uint32_t)hi << 16);
}

__global__ void sqcvt_kernel(const float* __restrict__ x, float* __restrict__ sq,
                             uint8_t* __restrict__ q, int rows) {
    int warp = (blockIdx.x * blockDim.x + threadIdx.x) >> 5;
    int lane = threadIdx.x & 31;
    if (warp >= rows) return;
    const float4* xr = reinterpret_cast<const float4*>(x) + (size_t)warp * (DDIM / 4);
    float4 v[4];
    float s = 0.f;
#pragma unroll
    for (int i = 0; i < 4; i++) {
        v[i] = xr[lane * 4 + i];
        s += v[i].x * v[i].x + v[i].y * v[i].y + v[i].z * v[i].z + v[i].w * v[i].w;
    }
    uint4 u;
    u.x = pack4_e4m3(v[0]); u.y = pack4_e4m3(v[1]);
    u.z = pack4_e4m3(v[2]); u.w = pack4_e4m3(v[3]);
    *reinterpret_cast<uint4*>(q + (size_t)warp * DDIM + lane * 16) = u;
#pragma unroll
    for (int o = 16; o; o >>= 1) s += __shfl_xor_sync(0xffffffffu, s, o);
    if (lane == 0) sq[warp] = s;
}

// ---------------- main coarse GEMM + candidate capture ----------------------
// smem per stage: A (128 rows x 64B, XOR-swizzled chunks) then B (128 x 64B).
// chunk address: row*64 + ((chunk ^ ((row>>1)&3)) * 16)
__global__ __launch_bounds__(NTHREADS, 2)
void som_mma_kernel() {
    extern __shared__ __align__(128) unsigned char smem[];
    __shared__ unsigned srow[BM];

    const int tid = threadIdx.x;
    const int wid = tid >> 5;
    const int lane = tid & 31;
    const int wm = wid >> 2;          // 0..1 (M half)
    const int wn = wid & 3;           // 0..3 (N quarter)
    const int m8 = lane >> 3;         // ldmatrix matrix id 0..3
    const int r8 = lane & 7;
    const int crow = lane >> 2;       // mma C row within 8
    const int qc = lane & 3;

    const int rowBase = blockIdx.x * BM;
    const int colBase = blockIdx.y * BN;

    const uint8_t* gA = g_zq + (size_t)rowBase * DDIM;
    const uint8_t* gB = g_pq + (size_t)colBase * DDIM;

    const uint32_t sbase = smem_u32(smem);

    if (tid < BM) srow[tid] = 0xFFFFFFFFu;

    // per-lane ldmatrix offsets (stage-relative); kf selects 32B k-half
    uint32_t aOff[2][4], bOff[2][2];
    {
        int rowW = wm * 64 + (m8 & 1) * 8 + r8;
        int sxa = (rowW >> 1) & 3;
#pragma unroll
        for (int kf = 0; kf < 2; kf++)
#pragma unroll
            for (int mi = 0; mi < 4; mi++)
                aOff[kf][mi] = (uint32_t)((rowW + mi * 16) * 64 +
                               (((kf * 2 + (m8 >> 1)) ^ sxa) << 4));
        int nW = wn * 32 + (m8 >> 1) * 8 + r8;
        int sxb = (nW >> 1) & 3;
#pragma unroll
        for (int kf = 0; kf < 2; kf++)
#pragma unroll
            for (int p = 0; p < 2; p++)
                bOff[kf][p] = (uint32_t)(A_STAGE_BYTES + (nW + p * 16) * 64 +
                              (((kf * 2 + (m8 & 1)) ^ sxb) << 4));
    }

    float acc[4][4][4];
#pragma unroll
    for (int mi = 0; mi < 4; mi++)
#pragma unroll
        for (int ni = 0; ni < 4; ni++)
#pragma unroll
            for (int c = 0; c < 4; c++) acc[mi][ni][c] = 0.f;

    const int KT = DDIM / BK;  // 8

    auto loadStage = [&](int st, int kt) {
        const uint32_t base = sbase + st * STAGE_BYTES;
#pragma unroll
        for (int i = 0; i < 2; i++) {         // A: 512 16B chunks
            int id = tid + i * NTHREADS;
            int r = id >> 2, c = id & 3;
            cp16(base + r * 64 + (((c ^ ((r >> 1) & 3))) << 4),
                 gA + (size_t)r * DDIM + kt * BK + c * 16);
        }
#pragma unroll
        for (int i = 0; i < 2; i++) {         // B: 512 16B chunks
            int id = tid + i * NTHREADS;
            int r = id >> 2, c = id & 3;
            cp16(base + A_STAGE_BYTES + r * 64 + (((c ^ ((r >> 1) & 3))) << 4),
                 gB + (size_t)r * DDIM + kt * BK + c * 16);
        }
        asm volatile("cp.async.commit_group;");
    };

    loadStage(0, 0);
    loadStage(1, 1);
    loadStage(2, 2);

    for (int kt = 0; kt < KT; kt++) {
        asm volatile("cp.async.wait_group 2;");
        __syncthreads();
        if (kt + 3 < KT) loadStage((kt + 3) & 3, kt + 3);

        const uint32_t stg = sbase + (kt & 3) * STAGE_BYTES;
#pragma unroll
        for (int kf = 0; kf < 2; kf++) {       // each kf = one k32 mma step
            uint32_t a[4][4];
#pragma unroll
            for (int mi = 0; mi < 4; mi++)
                LDSM4(a[mi][0], a[mi][1], a[mi][2], a[mi][3], stg + aOff[kf][mi]);
#pragma unroll
            for (int p = 0; p < 2; p++) {
                uint32_t b0, b1, b2, b3;
                LDSM4(b0, b1, b2, b3, stg + bOff[kf][p]);
#pragma unroll
                for (int mi = 0; mi < 4; mi++) {
                    mma_fp8(acc[mi][2 * p],     a[mi], b0, b1);
                    mma_fp8(acc[mi][2 * p + 1], a[mi], b2, b3);
                }
            }
        }
        __syncthreads();
    }

    // ---- epilogue: d = z2 - 2*dot + p2, per-row min, candidate append -------
#pragma unroll
    for (int mi = 0; mi < 4; mi++) {
#pragma unroll
        for (int h = 0; h < 2; h++) {
            int lrow = wm * 64 + mi * 16 + crow + h * 8;
            float z2v = g_z2[rowBase + lrow];
            float tmin = 3.4e38f;
#pragma unroll
            for (int ni = 0; ni < 4; ni++) {
                int gcol = colBase + wn * 32 + ni * 8 + 2 * qc;
                float d0 = (z2v - 2.0f * acc[mi][ni][2 * h])     + __ldg(&g_p2[gcol]);
                float d1 = (z2v - 2.0f * acc[mi][ni][2 * h + 1]) + __ldg(&g_p2[gcol + 1]);
                acc[mi][ni][2 * h] = d0;
                acc[mi][ni][2 * h + 1] = d1;
                tmin = fminf(tmin, fminf(d0, d1));
            }
            atomicMin(&srow[lrow], __float_as_uint(tmin));
        }
    }
    __syncthreads();

    if (tid < BM) atomicMin(&g_best[rowBase + tid], srow[tid]);

#pragma unroll
    for (int mi = 0; mi < 4; mi++) {
#pragma unroll
        for (int h = 0; h < 2; h++) {
            int lrow = wm * 64 + mi * 16 + crow + h * 8;
            int grow = rowBase + lrow;
            float gb = fminf(__uint_as_float(g_best[grow]),
                             __uint_as_float(srow[lrow]));
            float thr = gb + COARSE_THR;
#pragma unroll
            for (int ni = 0; ni < 4; ni++) {
                int gcol = colBase + wn * 32 + ni * 8 + 2 * qc;
#pragma unroll
                for (int e = 0; e < 2; e++) {
                    float d = acc[mi][ni][2 * h + e];
                    if (d < thr) {
                        int slot = atomicAdd(&g_ccnt[grow], 1);
                        if (slot < CAND_CAP) {
                            g_cval[(size_t)grow * CAND_CAP + slot] = d;
                            g_cidx[(size_t)grow * CAND_CAP + slot] = gcol + e;
                        }
                    }
                }
            }
        }
    }
}

// ---------------- exact refinement + output ---------------------------------
__global__ void refine_kernel(const float* __restrict__ z,
                              const float* __restrict__ proto, int Mtot,
                              float* __restrict__ outW,
                              float* __restrict__ outIdxF,
                              int* __restrict__ outIdxI) {
    int warp = (blockIdx.x * blockDim.x + threadIdx.x) >> 5;
    int lane = threadIdx.x & 31;
    const int row = warp;
    const float z2 = g_z2[row];

    float4 zr[4];
#pragma unroll
    for (int i = 0; i < 4; i++)
        zr[i] = reinterpret_cast<const float4*>(z + (size_t)row * DDIM)[i * 32 + lane];

    int cnt = g_ccnt[row];
    float bestD = 3.4e38f;
    int bestI = 0;

    if (cnt <= CAND_CAP) {
        for (int k = 0; k < cnt; k++) {
            int c = g_cidx[(size_t)row * CAND_CAP + k];
            const float4* pr = reinterpret_cast<const float4*>(proto + (size_t)c * DDIM);
            float dot = 0.f;
#pragma unroll
            for (int i = 0; i < 4; i++) {
                float4 pv = pr[i * 32 + lane];
                dot += zr[i].x * pv.x + zr[i].y * pv.y + zr[i].z * pv.z + zr[i].w * pv.w;
            }
#pragma unroll
            for (int o = 16; o; o >>= 1) dot += __shfl_xor_sync(0xffffffffu, dot, o);
            float d = (z2 - 2.0f * dot) + __ldg(&g_p2[c]);
            if (d < bestD || (d == bestD && c < bestI)) { bestD = d; bestI = c; }
        }
    } else {
        for (int c = 0; c < Mtot; c++) {
            const float4* pr = reinterpret_cast<const float4*>(proto + (size_t)c * DDIM);
            float dot = 0.f;
#pragma unroll
            for (int i = 0; i < 4; i++) {
                float4 pv = pr[i * 32 + lane];
                dot += zr[i].x * pv.x + zr[i].y * pv.y + zr[i].z * pv.z + zr[i].w * pv.w;
            }
#pragma unroll
            for (int o = 16; o; o >>= 1) dot += __shfl_xor_sync(0xffffffffu, dot, o);
            float d = (z2 - 2.0f * dot) + __ldg(&g_p2[c]);
            if (d < bestD) { bestD = d; bestI = c; }
        }
    }

    if (lane == 0) {
        if (outIdxF) outIdxF[row] = (float)bestI;
        if (outIdxI) outIdxI[row] = bestI;
    }
    if (outW) {
        const float4* pr = reinterpret_cast<const float4*>(proto + (size_t)bestI * DDIM);
        float4* ow = reinterpret_cast<float4*>(outW + (size_t)row * DDIM);
#pragma unroll
        for (int i = 0; i < 4; i++) ow[i * 32 + lane] = pr[i * 32 + lane];
    }
}

// ---------------------------------------------------------------------------
extern "C" void kernel_launch(void* const* d_in, const int* in_sizes, int n_in,
                              void* d_out, int out_size) {
    const float* z = (const float*)d_in[0];
    const float* p = (const float*)d_in[1];
    int N = in_sizes[0] / DDIM;
    int M = in_sizes[1] / DDIM;

    float* p2; float* z2; uint8_t* zq; uint8_t* pq;
    cudaGetSymbolAddress((void**)&p2, g_p2);
    cudaGetSymbolAddress((void**)&z2, g_z2);
    cudaGetSymbolAddress((void**)&zq, g_zq);
    cudaGetSymbolAddress((void**)&pq, g_pq);

    zero_kernel<<<(N + 255) / 256, 256>>>(N);
    sqcvt_kernel<<<(M * 32 + 255) / 256, 256>>>(p, p2, pq, M);
    sqcvt_kernel<<<(N * 32 + 255) / 256, 256>>>(z, z2, zq, N);

    cudaFuncSetAttribute(som_mma_kernel,
                         cudaFuncAttributeMaxDynamicSharedMemorySize, SMEM_BYTES);
    dim3 grid(N / BM, M / BN);   // x = row tiles (fast), y = col tiles
    som_mma_kernel<<<grid, NTHREADS, SMEM_BYTES>>>();

    float* outW = nullptr;
    float* outIdxF = nullptr;
    int* outIdxI = nullptr;
    long long nd = (long long)N * DDIM;
    if ((long long)out_size >= nd) {
        outW = (float*)d_out;
        if ((long long)out_size >= nd + N) outIdxF = (float*)d_out + nd;
    } else if (out_size == N) {
        outIdxI = (int*)d_out;
    }

    refine_kernel<<<(N * 32) / 256, 256>>>(z, p, M, outW, outIdxF, outIdxI);
}

// round 7
// speedup vs baseline: 1.4111x; 1.0101x over previous
#include <cuda_runtime.h>
#include <cuda_bf16.h>
#include <cuda_fp8.h>
#include <cstdint>

// SOM layer: coarse fp8(e4m3) mma.sync GEMM (scores + candidate capture) then
// exact fp32 refinement of candidates -> argmin identical to reference.
// R7: fully-unrolled K loop (constant smem/global offsets, correct tail
// cp.async.wait_group immediates -- R6 under-waited at kt=6,7), single
// __syncthreads per stage, hoisted fragment loads.

#define DDIM 512
#define MAXN 32768
#define MAXM 4096
#define CAND_CAP 64
#define COARSE_THR 16.0f   // ~7 sigma of fp8 coarse-score error

#define BM 128
#define BN 128
#define BK 64              // fp8 elements per k-tile = 64 bytes/row
#define NTHREADS 256       // 8 warps: 2(m) x 4(n), warp tile 64x32
#define STAGES 4
#define KT (DDIM / BK)     // 8
#define A_STAGE_BYTES (BM * 64)            // 8192
#define B_STAGE_BYTES (BN * 64)            // 8192
#define STAGE_BYTES (A_STAGE_BYTES + B_STAGE_BYTES)  // 16384
#define SMEM_BYTES (STAGES * STAGE_BYTES)  // 65536

// ---------------- device global scratch (allocation-free rule) --------------
__device__ float g_p2[MAXM];
__device__ float g_z2[MAXN];
__device__ __align__(128) uint8_t g_zq[MAXN * DDIM];   // 16MB e4m3
__device__ __align__(128) uint8_t g_pq[MAXM * DDIM];   // 2MB  e4m3
__device__ float    g_cval[(size_t)MAXN * CAND_CAP];
__device__ int      g_cidx[(size_t)MAXN * CAND_CAP];
__device__ int      g_ccnt[MAXN];
__device__ unsigned g_best[MAXN];

// ---------------- helpers ----------------------------------------------------
__device__ __forceinline__ uint32_t smem_u32(const void* p) {
    uint32_t a;
    asm("{ .reg .u64 t; cvta.to.shared.u64 t, %1; cvt.u32.u64 %0, t; }"
        : "=r"(a) : "l"(p));
    return a;
}
__device__ __forceinline__ void cp16(uint32_t dst, const void* src) {
    asm volatile("cp.async.cg.shared.global [%0], [%1], 16;" :: "r"(dst), "l"(src));
}
template <int N> __device__ __forceinline__ void cp_wait() {
    asm volatile("cp.async.wait_group %0;" :: "n"(N));
}
__device__ __forceinline__ void mma_fp8(float* c, const uint32_t* a,
                                        uint32_t b0, uint32_t b1) {
    asm volatile(
        "mma.sync.aligned.m16n8k32.row.col.f32.e4m3.e4m3.f32 "
        "{%0,%1,%2,%3}, {%4,%5,%6,%7}, {%8,%9}, {%0,%1,%2,%3};"
        : "+f"(c[0]), "+f"(c[1]), "+f"(c[2]), "+f"(c[3])
        : "r"(a[0]), "r"(a[1]), "r"(a[2]), "r"(a[3]), "r"(b0), "r"(b1));
}
#define LDSM4(r0, r1, r2, r3, addr) \
    asm volatile("ldmatrix.sync.aligned.m8n8.x4.shared.b16 {%0,%1,%2,%3}, [%4];" \
                 : "=r"(r0), "=r"(r1), "=r"(r2), "=r"(r3) : "r"(addr))

// ---------------- init / fused sum-of-squares + fp8 convert ------------------
__global__ void zero_kernel(int n) {
    int i = blockIdx.x * blockDim.x + threadIdx.x;
    if (i < n) { g_ccnt[i] = 0; g_best[i] = 0x7F800000u; }
}

__device__ __forceinline__ uint32_t pack4_e4m3(float4 v) {
    __nv_fp8x2_storage_t lo = __nv_cvt_float2_to_fp8x2(make_float2(v.x, v.y),
                                                       __NV_SATFINITE, __NV_E4M3);
    __nv_fp8x2_storage_t hi = __nv_cvt_float2_to_fp8x2(make_float2(v.z, v.w),
                                                       __NV_SATFINITE, __NV_E4M3);
    return (uint32_t)lo | ((uint32_t)hi << 16);
}

__global__ void sqcvt_kernel(const float* __restrict__ x, float* __restrict__ sq,
                             uint8_t* __restrict__ q, int rows) {
    int warp = (blockIdx.x * blockDim.x + threadIdx.x) >> 5;
    int lane = threadIdx.x & 31;
    if (warp >= rows) return;
    const float4* xr = reinterpret_cast<const float4*>(x) + (size_t)warp * (DDIM / 4);
    float4 v[4];
    float s = 0.f;
#pragma unroll
    for (int i = 0; i < 4; i++) {
        v[i] = xr[lane * 4 + i];
        s += v[i].x * v[i].x + v[i].y * v[i].y + v[i].z * v[i].z + v[i].w * v[i].w;
    }
    uint4 u;
    u.x = pack4_e4m3(v[0]); u.y = pack4_e4m3(v[1]);
    u.z = pack4_e4m3(v[2]); u.w = pack4_e4m3(v[3]);
    *reinterpret_cast<uint4*>(q + (size_t)warp * DDIM + lane * 16) = u;
#pragma unroll
    for (int o = 16; o; o >>= 1) s += __shfl_xor_sync(0xffffffffu, s, o);
    if (lane == 0) sq[warp] = s;
}

// ---------------- main coarse GEMM + candidate capture ----------------------
// smem per stage: A (128 rows x 64B, XOR-swizzled chunks) then B (128 x 64B).
// chunk address: row*64 + ((chunk ^ ((row>>1)&3)) * 16)
__global__ __launch_bounds__(NTHREADS, 2)
void som_mma_kernel() {
    extern __shared__ __align__(128) unsigned char smem[];
    __shared__ unsigned srow[BM];

    const int tid = threadIdx.x;
    const int wid = tid >> 5;
    const int lane = tid & 31;
    const int wm = wid >> 2;          // 0..1 (M half)
    const int wn = wid & 3;           // 0..3 (N quarter)
    const int m8 = lane >> 3;         // ldmatrix matrix id 0..3
    const int r8 = lane & 7;
    const int crow = lane >> 2;       // mma C row within 8
    const int qc = lane & 3;

    const int rowBase = blockIdx.x * BM;
    const int colBase = blockIdx.y * BN;

    const uint8_t* gA = g_zq + (size_t)rowBase * DDIM;
    const uint8_t* gB = g_pq + (size_t)colBase * DDIM;

    const uint32_t sbase = smem_u32(smem);

    if (tid < BM) srow[tid] = 0xFFFFFFFFu;

    // per-thread cp.async coordinates (loop-invariant)
    const int cp_r0 = tid >> 2;                 // A/B row for chunk set 0
    const int cp_r1 = (tid + NTHREADS) >> 2;    // row for chunk set 1
    const int cp_c0 = tid & 3;
    const uint32_t cpA0 = (uint32_t)(cp_r0 * 64 + (((cp_c0 ^ ((cp_r0 >> 1) & 3))) << 4));
    const uint32_t cpA1 = (uint32_t)(cp_r1 * 64 + (((cp_c0 ^ ((cp_r1 >> 1) & 3))) << 4));
    const uint8_t* srcA0 = gA + (size_t)cp_r0 * DDIM + cp_c0 * 16;
    const uint8_t* srcA1 = gA + (size_t)cp_r1 * DDIM + cp_c0 * 16;
    const uint8_t* srcB0 = gB + (size_t)cp_r0 * DDIM + cp_c0 * 16;
    const uint8_t* srcB1 = gB + (size_t)cp_r1 * DDIM + cp_c0 * 16;

    // per-lane ldmatrix offsets (stage-relative); kf selects 32B k-half
    uint32_t aOff[2][4], bOff[2][2];
    {
        int rowW = wm * 64 + (m8 & 1) * 8 + r8;
        int sxa = (rowW >> 1) & 3;
#pragma unroll
        for (int kf = 0; kf < 2; kf++)
#pragma unroll
            for (int mi = 0; mi < 4; mi++)
                aOff[kf][mi] = (uint32_t)((rowW + mi * 16) * 64 +
                               (((kf * 2 + (m8 >> 1)) ^ sxa) << 4));
        int nW = wn * 32 + (m8 >> 1) * 8 + r8;
        int sxb = (nW >> 1) & 3;
#pragma unroll
        for (int kf = 0; kf < 2; kf++)
#pragma unroll
            for (int p = 0; p < 2; p++)
                bOff[kf][p] = (uint32_t)(A_STAGE_BYTES + (nW + p * 16) * 64 +
                              (((kf * 2 + (m8 & 1)) ^ sxb) << 4));
    }

    float acc[4][4][4];
#pragma unroll
    for (int mi = 0; mi < 4; mi++)
#pragma unroll
        for (int ni = 0; ni < 4; ni++)
#pragma unroll
            for (int c = 0; c < 4; c++) acc[mi][ni][c] = 0.f;

    // stage loader: all offsets constant under full unroll
    auto loadStage = [&](int st, int kt) {
        const uint32_t base = sbase + st * STAGE_BYTES;
        const int go = kt * BK;
        cp16(base + cpA0, srcA0 + go);
        cp16(base + cpA1, srcA1 + go);
        cp16(base + A_STAGE_BYTES + cpA0, srcB0 + go);
        cp16(base + A_STAGE_BYTES + cpA1, srcB1 + go);
        asm volatile("cp.async.commit_group;");
    };

    loadStage(0, 0);
    loadStage(1, 1);
    loadStage(2, 2);

#pragma unroll
    for (int kt = 0; kt < KT; kt++) {
        // correct tail waits: groups 0..kt must be complete before compute(kt)
        if (kt <= KT - 3)      cp_wait<2>();
        else if (kt == KT - 2) cp_wait<1>();
        else                   cp_wait<0>();
        __syncthreads();   // also orders: all warps done with stage (kt-1)&3
        if (kt + 3 < KT) loadStage((kt + 3) & 3, kt + 3);

        const uint32_t stg = sbase + (kt & 3) * STAGE_BYTES;

        // hoist: B kf0, A kf0, B kf1 -> compute kf0 -> A kf1 -> compute kf1
        uint32_t b[2][2][4];
        uint32_t a[4][4];
        LDSM4(b[0][0][0], b[0][0][1], b[0][0][2], b[0][0][3], stg + bOff[0][0]);
        LDSM4(b[0][1][0], b[0][1][1], b[0][1][2], b[0][1][3], stg + bOff[0][1]);
#pragma unroll
        for (int mi = 0; mi < 4; mi++)
            LDSM4(a[mi][0], a[mi][1], a[mi][2], a[mi][3], stg + aOff[0][mi]);
        LDSM4(b[1][0][0], b[1][0][1], b[1][0][2], b[1][0][3], stg + bOff[1][0]);
        LDSM4(b[1][1][0], b[1][1][1], b[1][1][2], b[1][1][3], stg + bOff[1][1]);

#pragma unroll
        for (int p = 0; p < 2; p++)
#pragma unroll
            for (int mi = 0; mi < 4; mi++) {
                mma_fp8(acc[mi][2 * p],     a[mi], b[0][p][0], b[0][p][1]);
                mma_fp8(acc[mi][2 * p + 1], a[mi], b[0][p][2], b[0][p][3]);
            }

#pragma unroll
        for (int mi = 0; mi < 4; mi++)
            LDSM4(a[mi][0], a[mi][1], a[mi][2], a[mi][3], stg + aOff[1][mi]);

#pragma unroll
        for (int p = 0; p < 2; p++)
#pragma unroll
            for (int mi = 0; mi < 4; mi++) {
                mma_fp8(acc[mi][2 * p],     a[mi], b[1][p][0], b[1][p][1]);
                mma_fp8(acc[mi][2 * p + 1], a[mi], b[1][p][2], b[1][p][3]);
            }
    }

    // ---- epilogue: d = z2 - 2*dot + p2, per-row min, candidate append -------
#pragma unroll
    for (int mi = 0; mi < 4; mi++) {
#pragma unroll
        for (int h = 0; h < 2; h++) {
            int lrow = wm * 64 + mi * 16 + crow + h * 8;
            float z2v = g_z2[rowBase + lrow];
            float tmin = 3.4e38f;
#pragma unroll
            for (int ni = 0; ni < 4; ni++) {
                int gcol = colBase + wn * 32 + ni * 8 + 2 * qc;
                float d0 = (z2v - 2.0f * acc[mi][ni][2 * h])     + __ldg(&g_p2[gcol]);
                float d1 = (z2v - 2.0f * acc[mi][ni][2 * h + 1]) + __ldg(&g_p2[gcol + 1]);
                acc[mi][ni][2 * h] = d0;
                acc[mi][ni][2 * h + 1] = d1;
                tmin = fminf(tmin, fminf(d0, d1));
            }
            atomicMin(&srow[lrow], __float_as_uint(tmin));
        }
    }
    __syncthreads();

    if (tid < BM) atomicMin(&g_best[rowBase + tid], srow[tid]);

#pragma unroll
    for (int mi = 0; mi < 4; mi++) {
#pragma unroll
        for (int h = 0; h < 2; h++) {
            int lrow = wm * 64 + mi * 16 + crow + h * 8;
            int grow = rowBase + lrow;
            float gb = fminf(__uint_as_float(g_best[grow]),
                             __uint_as_float(srow[lrow]));
            float thr = gb + COARSE_THR;
#pragma unroll
            for (int ni = 0; ni < 4; ni++) {
                int gcol = colBase + wn * 32 + ni * 8 + 2 * qc;
#pragma unroll
                for (int e = 0; e < 2; e++) {
                    float d = acc[mi][ni][2 * h + e];
                    if (d < thr) {
                        int slot = atomicAdd(&g_ccnt[grow], 1);
                        if (slot < CAND_CAP) {
                            g_cval[(size_t)grow * CAND_CAP + slot] = d;
                            g_cidx[(size_t)grow * CAND_CAP + slot] = gcol + e;
                        }
                    }
                }
            }
        }
    }
}

// ---------------- exact refinement + output ---------------------------------
__global__ void refine_kernel(const float* __restrict__ z,
                              const float* __restrict__ proto, int Mtot,
                              float* __restrict__ outW,
                              float* __restrict__ outIdxF,
                              int* __restrict__ outIdxI) {
    int warp = (blockIdx.x * blockDim.x + threadIdx.x) >> 5;
    int lane = threadIdx.x & 31;
    const int row = warp;
    const float z2 = g_z2[row];

    float4 zr[4];
#pragma unroll
    for (int i = 0; i < 4; i++)
        zr[i] = reinterpret_cast<const float4*>(z + (size_t)row * DDIM)[i * 32 + lane];

    int cnt = g_ccnt[row];
    float bestD = 3.4e38f;
    int bestI = 0;

    if (cnt <= CAND_CAP) {
        for (int k = 0; k < cnt; k++) {
            int c = g_cidx[(size_t)row * CAND_CAP + k];
            const float4* pr = reinterpret_cast<const float4*>(proto + (size_t)c * DDIM);
            float dot = 0.f;
#pragma unroll
            for (int i = 0; i < 4; i++) {
                float4 pv = pr[i * 32 + lane];
                dot += zr[i].x * pv.x + zr[i].y * pv.y + zr[i].z * pv.z + zr[i].w * pv.w;
            }
#pragma unroll
            for (int o = 16; o; o >>= 1) dot += __shfl_xor_sync(0xffffffffu, dot, o);
            float d = (z2 - 2.0f * dot) + __ldg(&g_p2[c]);
            if (d < bestD || (d == bestD && c < bestI)) { bestD = d; bestI = c; }
        }
    } else {
        for (int c = 0; c < Mtot; c++) {
            const float4* pr = reinterpret_cast<const float4*>(proto + (size_t)c * DDIM);
            float dot = 0.f;
#pragma unroll
            for (int i = 0; i < 4; i++) {
                float4 pv = pr[i * 32 + lane];
                dot += zr[i].x * pv.x + zr[i].y * pv.y + zr[i].z * pv.z + zr[i].w * pv.w;
            }
#pragma unroll
            for (int o = 16; o; o >>= 1) dot += __shfl_xor_sync(0xffffffffu, dot, o);
            float d = (z2 - 2.0f * dot) + __ldg(&g_p2[c]);
            if (d < bestD) { bestD = d; bestI = c; }
        }
    }

    if (lane == 0) {
        if (outIdxF) outIdxF[row] = (float)bestI;
        if (outIdxI) outIdxI[row] = bestI;
    }
    if (outW) {
        const float4* pr = reinterpret_cast<const float4*>(proto + (size_t)bestI * DDIM);
        float4* ow = reinterpret_cast<float4*>(outW + (size_t)row * DDIM);
#pragma unroll
        for (int i = 0; i < 4; i++) ow[i * 32 + lane] = pr[i * 32 + lane];
    }
}

// ---------------------------------------------------------------------------
extern "C" void kernel_launch(void* const* d_in, const int* in_sizes, int n_in,
                              void* d_out, int out_size) {
    const float* z = (const float*)d_in[0];
    const float* p = (const float*)d_in[1];
    int N = in_sizes[0] / DDIM;
    int M = in_sizes[1] / DDIM;

    float* p2; float* z2; uint8_t* zq; uint8_t* pq;
    cudaGetSymbolAddress((void**)&p2, g_p2);
    cudaGetSymbolAddress((void**)&z2, g_z2);
    cudaGetSymbolAddress((void**)&zq, g_zq);
    cudaGetSymbolAddress((void**)&pq, g_pq);

    zero_kernel<<<(N + 255) / 256, 256>>>(N);
    sqcvt_kernel<<<(M * 32 + 255) / 256, 256>>>(p, p2, pq, M);
    sqcvt_kernel<<<(N * 32 + 255) / 256, 256>>>(z, z2, zq, N);

    cudaFuncSetAttribute(som_mma_kernel,
                         cudaFuncAttributeMaxDynamicSharedMemorySize, SMEM_BYTES);
    dim3 grid(N / BM, M / BN);   // x = row tiles (fast), y = col tiles
    som_mma_kernel<<<grid, NTHREADS, SMEM_BYTES>>>();

    float* outW = nullptr;
    float* outIdxF = nullptr;
    int* outIdxI = nullptr;
    long long nd = (long long)N * DDIM;
    if ((long long)out_size >= nd) {
        outW = (float*)d_out;
        if ((long long)out_size >= nd + N) outIdxF = (float*)d_out + nd;
    } else if (out_size == N) {
        outIdxI = (int*)d_out;
    }

    refine_kernel<<<(N * 32) / 256, 256>>>(z, p, M, outW, outIdxF, outIdxI);
}

// round 8
// speedup vs baseline: 1.6829x; 1.1926x over previous
#include <cuda_runtime.h>
#include <cuda_fp16.h>
#include <cstdint>

// SOM layer: coarse fp16 (f16-accumulate) mma.sync GEMM (scores + candidate
// capture) then exact fp32 refinement -> argmin identical to reference.
// R8: R7 cycle audit showed tensor pipe saturated at rt=16/SMSP for fp32-acc
// HMMA (= ncu 51% of peak => peak is the f16-acc rate). Switch to native
// m16n8k16.f16.f16.f16.f16 for the 2x accumulate rate. Coarse error sigma~0.4
// << margin 16, exact refine unchanged.

#define DDIM 512
#define MAXN 32768
#define MAXM 4096
#define CAND_CAP 64
#define COARSE_THR 16.0f

#define BM 128
#define BN 128
#define BK 32              // f16 elements per k-tile = 64 bytes/row
#define NTHREADS 256       // 8 warps: 2(m) x 4(n), warp tile 64x32
#define STAGES 4
#define KT (DDIM / BK)     // 16
#define A_STAGE_BYTES (BM * 64)            // 8192
#define B_STAGE_BYTES (BN * 64)            // 8192
#define STAGE_BYTES (A_STAGE_BYTES + B_STAGE_BYTES)  // 16384
#define SMEM_BYTES (STAGES * STAGE_BYTES)  // 65536

// ---------------- device global scratch (allocation-free rule) --------------
__device__ float g_p2[MAXM];
__device__ float g_z2[MAXN];
__device__ __align__(128) __half g_zh[MAXN * DDIM];   // 32MB
__device__ __align__(128) __half g_ph[MAXM * DDIM];   // 4MB
__device__ float    g_cval[(size_t)MAXN * CAND_CAP];
__device__ int      g_cidx[(size_t)MAXN * CAND_CAP];
__device__ int      g_ccnt[MAXN];
__device__ unsigned g_best[MAXN];

// ---------------- helpers ----------------------------------------------------
__device__ __forceinline__ uint32_t smem_u32(const void* p) {
    uint32_t a;
    asm("{ .reg .u64 t; cvta.to.shared.u64 t, %1; cvt.u32.u64 %0, t; }"
        : "=r"(a) : "l"(p));
    return a;
}
__device__ __forceinline__ void cp16(uint32_t dst, const void* src) {
    asm volatile("cp.async.cg.shared.global [%0], [%1], 16;" :: "r"(dst), "l"(src));
}
template <int N> __device__ __forceinline__ void cp_wait() {
    asm volatile("cp.async.wait_group %0;" :: "n"(N));
}
// f16-accumulate HMMA: D(f16x2 x2) = A(f16) * B(f16) + D
__device__ __forceinline__ void mma_f16acc(uint32_t* c, const uint32_t* a,
                                           uint32_t b0, uint32_t b1) {
    asm volatile(
        "mma.sync.aligned.m16n8k16.row.col.f16.f16.f16.f16 "
        "{%0,%1}, {%2,%3,%4,%5}, {%6,%7}, {%0,%1};"
        : "+r"(c[0]), "+r"(c[1])
        : "r"(a[0]), "r"(a[1]), "r"(a[2]), "r"(a[3]), "r"(b0), "r"(b1));
}
#define LDSM4(r0, r1, r2, r3, addr) \
    asm volatile("ldmatrix.sync.aligned.m8n8.x4.shared.b16 {%0,%1,%2,%3}, [%4];" \
                 : "=r"(r0), "=r"(r1), "=r"(r2), "=r"(r3) : "r"(addr))

// ---------------- init / fused sum-of-squares + fp16 convert -----------------
__global__ void zero_kernel(int n) {
    int i = blockIdx.x * blockDim.x + threadIdx.x;
    if (i < n) { g_ccnt[i] = 0; g_best[i] = 0x7F800000u; }
}

__device__ __forceinline__ uint32_t pack2_h(float a, float b) {
    __half2 t = __float22half2_rn(make_float2(a, b));
    return *reinterpret_cast<uint32_t*>(&t);
}

__global__ void sqcvt_kernel(const float* __restrict__ x, float* __restrict__ sq,
                             __half* __restrict__ q, int rows) {
    int warp = (blockIdx.x * blockDim.x + threadIdx.x) >> 5;
    int lane = threadIdx.x & 31;
    if (warp >= rows) return;
    const float4* xr = reinterpret_cast<const float4*>(x) + (size_t)warp * (DDIM / 4);
    float s = 0.f;
#pragma unroll
    for (int i = 0; i < 2; i++) {
        float4 v0 = xr[lane * 4 + i * 2];
        float4 v1 = xr[lane * 4 + i * 2 + 1];
        s += v0.x * v0.x + v0.y * v0.y + v0.z * v0.z + v0.w * v0.w;
        s += v1.x * v1.x + v1.y * v1.y + v1.z * v1.z + v1.w * v1.w;
        uint4 u;
        u.x = pack2_h(v0.x, v0.y); u.y = pack2_h(v0.z, v0.w);
        u.z = pack2_h(v1.x, v1.y); u.w = pack2_h(v1.z, v1.w);
        *reinterpret_cast<uint4*>(q + (size_t)warp * DDIM + lane * 16 + i * 8) = u;
    }
#pragma unroll
    for (int o = 16; o; o >>= 1) s += __shfl_xor_sync(0xffffffffu, s, o);
    if (lane == 0) sq[warp] = s;
}

// ---------------- main coarse GEMM + candidate capture ----------------------
// smem per stage: A (128 rows x 64B, XOR-swizzled chunks) then B (128 x 64B).
// chunk address: row*64 + ((chunk ^ ((row>>1)&3)) * 16)
__global__ __launch_bounds__(NTHREADS, 2)
void som_mma_kernel() {
    extern __shared__ __align__(128) unsigned char smem[];
    __shared__ unsigned srow[BM];

    const int tid = threadIdx.x;
    const int wid = tid >> 5;
    const int lane = tid & 31;
    const int wm = wid >> 2;          // 0..1 (M half)
    const int wn = wid & 3;           // 0..3 (N quarter)
    const int m8 = lane >> 3;         // ldmatrix matrix id 0..3
    const int r8 = lane & 7;
    const int crow = lane >> 2;       // mma C row within 8
    const int qc = lane & 3;

    const int rowBase = blockIdx.x * BM;
    const int colBase = blockIdx.y * BN;

    const __half* gA = g_zh + (size_t)rowBase * DDIM;
    const __half* gB = g_ph + (size_t)colBase * DDIM;

    const uint32_t sbase = smem_u32(smem);

    if (tid < BM) srow[tid] = 0xFFFFFFFFu;

    // per-thread cp.async coordinates (loop-invariant); rows are 64B = 32 f16
    const int cp_r0 = tid >> 2;
    const int cp_r1 = (tid + NTHREADS) >> 2;
    const int cp_c0 = tid & 3;
    const uint32_t cpA0 = (uint32_t)(cp_r0 * 64 + (((cp_c0 ^ ((cp_r0 >> 1) & 3))) << 4));
    const uint32_t cpA1 = (uint32_t)(cp_r1 * 64 + (((cp_c0 ^ ((cp_r1 >> 1) & 3))) << 4));
    const __half* srcA0 = gA + (size_t)cp_r0 * DDIM + cp_c0 * 8;
    const __half* srcA1 = gA + (size_t)cp_r1 * DDIM + cp_c0 * 8;
    const __half* srcB0 = gB + (size_t)cp_r0 * DDIM + cp_c0 * 8;
    const __half* srcB1 = gB + (size_t)cp_r1 * DDIM + cp_c0 * 8;

    // per-lane ldmatrix offsets (stage-relative); kf selects 32B k-half (k16)
    uint32_t aOff[2][4], bOff[2][2];
    {
        int rowW = wm * 64 + (m8 & 1) * 8 + r8;
        int sxa = (rowW >> 1) & 3;
#pragma unroll
        for (int kf = 0; kf < 2; kf++)
#pragma unroll
            for (int mi = 0; mi < 4; mi++)
                aOff[kf][mi] = (uint32_t)((rowW + mi * 16) * 64 +
                               (((kf * 2 + (m8 >> 1)) ^ sxa) << 4));
        int nW = wn * 32 + (m8 >> 1) * 8 + r8;
        int sxb = (nW >> 1) & 3;
#pragma unroll
        for (int kf = 0; kf < 2; kf++)
#pragma unroll
            for (int p = 0; p < 2; p++)
                bOff[kf][p] = (uint32_t)(A_STAGE_BYTES + (nW + p * 16) * 64 +
                              (((kf * 2 + (m8 & 1)) ^ sxb) << 4));
    }

    // f16x2 accumulators: [mi][n8 index][row-half]; 32 regs total
    uint32_t acc[4][4][2];
    const uint32_t hzero = 0u;
#pragma unroll
    for (int mi = 0; mi < 4; mi++)
#pragma unroll
        for (int ni = 0; ni < 4; ni++) { acc[mi][ni][0] = hzero; acc[mi][ni][1] = hzero; }

    auto loadStage = [&](int st, int kt) {
        const uint32_t base = sbase + st * STAGE_BYTES;
        const int go = kt * BK;
        cp16(base + cpA0, srcA0 + go);
        cp16(base + cpA1, srcA1 + go);
        cp16(base + A_STAGE_BYTES + cpA0, srcB0 + go);
        cp16(base + A_STAGE_BYTES + cpA1, srcB1 + go);
        asm volatile("cp.async.commit_group;");
    };

    loadStage(0, 0);
    loadStage(1, 1);
    loadStage(2, 2);

#pragma unroll
    for (int kt = 0; kt < KT; kt++) {
        if (kt <= KT - 3)      cp_wait<2>();
        else if (kt == KT - 2) cp_wait<1>();
        else                   cp_wait<0>();
        __syncthreads();
        if (kt + 3 < KT) loadStage((kt + 3) & 3, kt + 3);

        const uint32_t stg = sbase + (kt & 3) * STAGE_BYTES;

        uint32_t b[2][2][4];
        uint32_t a[4][4];
        LDSM4(b[0][0][0], b[0][0][1], b[0][0][2], b[0][0][3], stg + bOff[0][0]);
        LDSM4(b[0][1][0], b[0][1][1], b[0][1][2], b[0][1][3], stg + bOff[0][1]);
#pragma unroll
        for (int mi = 0; mi < 4; mi++)
            LDSM4(a[mi][0], a[mi][1], a[mi][2], a[mi][3], stg + aOff[0][mi]);
        LDSM4(b[1][0][0], b[1][0][1], b[1][0][2], b[1][0][3], stg + bOff[1][0]);
        LDSM4(b[1][1][0], b[1][1][1], b[1][1][2], b[1][1][3], stg + bOff[1][1]);

#pragma unroll
        for (int p = 0; p < 2; p++)
#pragma unroll
            for (int mi = 0; mi < 4; mi++) {
                mma_f16acc(acc[mi][2 * p],     a[mi], b[0][p][0], b[0][p][1]);
                mma_f16acc(acc[mi][2 * p + 1], a[mi], b[0][p][2], b[0][p][3]);
            }

#pragma unroll
        for (int mi = 0; mi < 4; mi++)
            LDSM4(a[mi][0], a[mi][1], a[mi][2], a[mi][3], stg + aOff[1][mi]);

#pragma unroll
        for (int p = 0; p < 2; p++)
#pragma unroll
            for (int mi = 0; mi < 4; mi++) {
                mma_f16acc(acc[mi][2 * p],     a[mi], b[1][p][0], b[1][p][1]);
                mma_f16acc(acc[mi][2 * p + 1], a[mi], b[1][p][2], b[1][p][3]);
            }
    }

    // ---- epilogue: unpack f16x2, d = z2 - 2*dot + p2, row min, cand append ---
    float dd[4][4][2][2];  // [mi][ni][h][e]
#pragma unroll
    for (int mi = 0; mi < 4; mi++) {
#pragma unroll
        for (int h = 0; h < 2; h++) {
            int lrow = wm * 64 + mi * 16 + crow + h * 8;
            float z2v = g_z2[rowBase + lrow];
            float tmin = 3.4e38f;
#pragma unroll
            for (int ni = 0; ni < 4; ni++) {
                int gcol = colBase + wn * 32 + ni * 8 + 2 * qc;
                float2 dv = __half22float2(
                    *reinterpret_cast<__half2*>(&acc[mi][ni][h]));
                float d0 = (z2v - 2.0f * dv.x) + __ldg(&g_p2[gcol]);
                float d1 = (z2v - 2.0f * dv.y) + __ldg(&g_p2[gcol + 1]);
                dd[mi][ni][h][0] = d0;
                dd[mi][ni][h][1] = d1;
                tmin = fminf(tmin, fminf(d0, d1));
            }
            atomicMin(&srow[lrow], __float_as_uint(tmin));
        }
    }
    __syncthreads();

    if (tid < BM) atomicMin(&g_best[rowBase + tid], srow[tid]);

#pragma unroll
    for (int mi = 0; mi < 4; mi++) {
#pragma unroll
        for (int h = 0; h < 2; h++) {
            int lrow = wm * 64 + mi * 16 + crow + h * 8;
            int grow = rowBase + lrow;
            float gb = fminf(__uint_as_float(g_best[grow]),
                             __uint_as_float(srow[lrow]));
            float thr = gb + COARSE_THR;
#pragma unroll
            for (int ni = 0; ni < 4; ni++) {
                int gcol = colBase + wn * 32 + ni * 8 + 2 * qc;
#pragma unroll
                for (int e = 0; e < 2; e++) {
                    float d = dd[mi][ni][h][e];
                    if (d < thr) {
                        int slot = atomicAdd(&g_ccnt[grow], 1);
                        if (slot < CAND_CAP) {
                            g_cval[(size_t)grow * CAND_CAP + slot] = d;
                            g_cidx[(size_t)grow * CAND_CAP + slot] = gcol + e;
                        }
                    }
                }
            }
        }
    }
}

// ---------------- exact refinement + output ---------------------------------
__global__ void refine_kernel(const float* __restrict__ z,
                              const float* __restrict__ proto, int Mtot,
                              float* __restrict__ outW,
                              float* __restrict__ outIdxF,
                              int* __restrict__ outIdxI) {
    int warp = (blockIdx.x * blockDim.x + threadIdx.x) >> 5;
    int lane = threadIdx.x & 31;
    const int row = warp;
    const float z2 = g_z2[row];

    float4 zr[4];
#pragma unroll
    for (int i = 0; i < 4; i++)
        zr[i] = reinterpret_cast<const float4*>(z + (size_t)row * DDIM)[i * 32 + lane];

    int cnt = g_ccnt[row];
    float bestD = 3.4e38f;
    int bestI = 0;

    if (cnt <= CAND_CAP) {
        for (int k = 0; k < cnt; k++) {
            int c = g_cidx[(size_t)row * CAND_CAP + k];
            const float4* pr = reinterpret_cast<const float4*>(proto + (size_t)c * DDIM);
            float dot = 0.f;
#pragma unroll
            for (int i = 0; i < 4; i++) {
                float4 pv = pr[i * 32 + lane];
                dot += zr[i].x * pv.x + zr[i].y * pv.y + zr[i].z * pv.z + zr[i].w * pv.w;
            }
#pragma unroll
            for (int o = 16; o; o >>= 1) dot += __shfl_xor_sync(0xffffffffu, dot, o);
            float d = (z2 - 2.0f * dot) + __ldg(&g_p2[c]);
            if (d < bestD || (d == bestD && c < bestI)) { bestD = d; bestI = c; }
        }
    } else {
        for (int c = 0; c < Mtot; c++) {
            const float4* pr = reinterpret_cast<const float4*>(proto + (size_t)c * DDIM);
            float dot = 0.f;
#pragma unroll
            for (int i = 0; i < 4; i++) {
                float4 pv = pr[i * 32 + lane];
                dot += zr[i].x * pv.x + zr[i].y * pv.y + zr[i].z * pv.z + zr[i].w * pv.w;
            }
#pragma unroll
            for (int o = 16; o; o >>= 1) dot += __shfl_xor_sync(0xffffffffu, dot, o);
            float d = (z2 - 2.0f * dot) + __ldg(&g_p2[c]);
            if (d < bestD) { bestD = d; bestI = c; }
        }
    }

    if (lane == 0) {
        if (outIdxF) outIdxF[row] = (float)bestI;
        if (outIdxI) outIdxI[row] = bestI;
    }
    if (outW) {
        const float4* pr = reinterpret_cast<const float4*>(proto + (size_t)bestI * DDIM);
        float4* ow = reinterpret_cast<float4*>(outW + (size_t)row * DDIM);
#pragma unroll
        for (int i = 0; i < 4; i++) ow[i * 32 + lane] = pr[i * 32 + lane];
    }
}

// ---------------------------------------------------------------------------
extern "C" void kernel_launch(void* const* d_in, const int* in_sizes, int n_in,
                              void* d_out, int out_size) {
    const float* z = (const float*)d_in[0];
    const float* p = (const float*)d_in[1];
    int N = in_sizes[0] / DDIM;
    int M = in_sizes[1] / DDIM;

    float* p2; float* z2; __half* zh; __half* ph;
    cudaGetSymbolAddress((void**)&p2, g_p2);
    cudaGetSymbolAddress((void**)&z2, g_z2);
    cudaGetSymbolAddress((void**)&zh, g_zh);
    cudaGetSymbolAddress((void**)&ph, g_ph);

    zero_kernel<<<(N + 255) / 256, 256>>>(N);
    sqcvt_kernel<<<(M * 32 + 255) / 256, 256>>>(p, p2, ph, M);
    sqcvt_kernel<<<(N * 32 + 255) / 256, 256>>>(z, z2, zh, N);

    cudaFuncSetAttribute(som_mma_kernel,
                         cudaFuncAttributeMaxDynamicSharedMemorySize, SMEM_BYTES);
    dim3 grid(N / BM, M / BN);   // x = row tiles (fast), y = col tiles
    som_mma_kernel<<<grid, NTHREADS, SMEM_BYTES>>>();

    float* outW = nullptr;
    float* outIdxF = nullptr;
    int* outIdxI = nullptr;
    long long nd = (long long)N * DDIM;
    if ((long long)out_size >= nd) {
        outW = (float*)d_out;
        if ((long long)out_size >= nd + N) outIdxF = (float*)d_out + nd;
    } else if (out_size == N) {
        outIdxI = (int*)d_out;
    }

    refine_kernel<<<(N * 32) / 256, 256>>>(z, p, M, outW, outIdxF, outIdxI);
}

// round 9
// speedup vs baseline: 1.8094x; 1.0752x over previous
#include <cuda_runtime.h>
#include <cuda_fp16.h>
#include <cstdint>

// SOM layer: coarse fp16 (f16-accumulate) mma.sync GEMM (scores + candidate
// capture) then exact fp32 refinement -> argmin identical to reference.
// R9: R8 showed tensor(65%) vs L1(58%) dead heat -> smem-bound. Warp tile
// 64x64 (CTA 128x256) cuts smem bytes/MAC 1.5x. f16x2 acc keeps 64 regs.

#define DDIM 512
#define MAXN 32768
#define MAXM 4096
#define CAND_CAP 64
#define COARSE_THR 16.0f

#define BM 128
#define BN 256
#define BK 32              // f16 elements per k-tile = 64 bytes/row
#define NTHREADS 256       // 8 warps: 2(m) x 4(n), warp tile 64x64
#define STAGES 3
#define KT (DDIM / BK)     // 16
#define A_STAGE_BYTES (BM * 64)            // 8192
#define B_STAGE_BYTES (BN * 64)            // 16384
#define STAGE_BYTES (A_STAGE_BYTES + B_STAGE_BYTES)  // 24576
#define SMEM_BYTES (STAGES * STAGE_BYTES)  // 73728

// ---------------- device global scratch (allocation-free rule) --------------
__device__ float g_p2[MAXM];
__device__ float g_z2[MAXN];
__device__ __align__(128) __half g_zh[MAXN * DDIM];   // 32MB
__device__ __align__(128) __half g_ph[MAXM * DDIM];   // 4MB
__device__ int      g_cidx[(size_t)MAXN * CAND_CAP];
__device__ int      g_ccnt[MAXN];
__device__ unsigned g_best[MAXN];

// ---------------- helpers ----------------------------------------------------
__device__ __forceinline__ uint32_t smem_u32(const void* p) {
    uint32_t a;
    asm("{ .reg .u64 t; cvta.to.shared.u64 t, %1; cvt.u32.u64 %0, t; }"
        : "=r"(a) : "l"(p));
    return a;
}
__device__ __forceinline__ void cp16(uint32_t dst, const void* src) {
    asm volatile("cp.async.cg.shared.global [%0], [%1], 16;" :: "r"(dst), "l"(src));
}
template <int N> __device__ __forceinline__ void cp_wait() {
    asm volatile("cp.async.wait_group %0;" :: "n"(N));
}
__device__ __forceinline__ void mma_f16acc(uint32_t* c, const uint32_t* a,
                                           uint32_t b0, uint32_t b1) {
    asm volatile(
        "mma.sync.aligned.m16n8k16.row.col.f16.f16.f16.f16 "
        "{%0,%1}, {%2,%3,%4,%5}, {%6,%7}, {%0,%1};"
        : "+r"(c[0]), "+r"(c[1])
        : "r"(a[0]), "r"(a[1]), "r"(a[2]), "r"(a[3]), "r"(b0), "r"(b1));
}
#define LDSM4(r0, r1, r2, r3, addr) \
    asm volatile("ldmatrix.sync.aligned.m8n8.x4.shared.b16 {%0,%1,%2,%3}, [%4];" \
                 : "=r"(r0), "=r"(r1), "=r"(r2), "=r"(r3) : "r"(addr))

// ---------------- init / fused sum-of-squares + fp16 convert -----------------
__global__ void zero_kernel(int n) {
    int i = blockIdx.x * blockDim.x + threadIdx.x;
    if (i < n) { g_ccnt[i] = 0; g_best[i] = 0x7F800000u; }
}

__device__ __forceinline__ uint32_t pack2_h(float a, float b) {
    __half2 t = __float22half2_rn(make_float2(a, b));
    return *reinterpret_cast<uint32_t*>(&t);
}

__global__ void sqcvt_kernel(const float* __restrict__ x, float* __restrict__ sq,
                             __half* __restrict__ q, int rows) {
    int warp = (blockIdx.x * blockDim.x + threadIdx.x) >> 5;
    int lane = threadIdx.x & 31;
    if (warp >= rows) return;
    const float4* xr = reinterpret_cast<const float4*>(x) + (size_t)warp * (DDIM / 4);
    float s = 0.f;
#pragma unroll
    for (int i = 0; i < 2; i++) {
        float4 v0 = xr[lane * 4 + i * 2];
        float4 v1 = xr[lane * 4 + i * 2 + 1];
        s += v0.x * v0.x + v0.y * v0.y + v0.z * v0.z + v0.w * v0.w;
        s += v1.x * v1.x + v1.y * v1.y + v1.z * v1.z + v1.w * v1.w;
        uint4 u;
        u.x = pack2_h(v0.x, v0.y); u.y = pack2_h(v0.z, v0.w);
        u.z = pack2_h(v1.x, v1.y); u.w = pack2_h(v1.z, v1.w);
        *reinterpret_cast<uint4*>(q + (size_t)warp * DDIM + lane * 16 + i * 8) = u;
    }
#pragma unroll
    for (int o = 16; o; o >>= 1) s += __shfl_xor_sync(0xffffffffu, s, o);
    if (lane == 0) sq[warp] = s;
}

// ---------------- main coarse GEMM + candidate capture ----------------------
// smem per stage: A (128 rows x 64B, XOR-swizzled chunks) then B (256 x 64B).
// chunk address: row*64 + ((chunk ^ ((row>>1)&3)) * 16)
__global__ __launch_bounds__(NTHREADS, 2)
void som_mma_kernel() {
    extern __shared__ __align__(128) unsigned char smem[];
    __shared__ unsigned srow[BM];

    const int tid = threadIdx.x;
    const int wid = tid >> 5;
    const int lane = tid & 31;
    const int wm = wid >> 2;          // 0..1 (M half)
    const int wn = wid & 3;           // 0..3 (N quarter, 64 cols each)
    const int m8 = lane >> 3;         // ldmatrix matrix id 0..3
    const int r8 = lane & 7;
    const int crow = lane >> 2;       // mma C row within 8
    const int qc = lane & 3;

    const int rowBase = blockIdx.x * BM;
    const int colBase = blockIdx.y * BN;

    const __half* gA = g_zh + (size_t)rowBase * DDIM;
    const __half* gB = g_ph + (size_t)colBase * DDIM;

    const uint32_t sbase = smem_u32(smem);

    if (tid < BM) srow[tid] = 0xFFFFFFFFu;

    // cp.async coords: A 512 chunks (2/thread), B 1024 chunks (4/thread)
    const int cp_c0 = tid & 3;
    int cpr[2];
    cpr[0] = tid >> 2; cpr[1] = (tid + NTHREADS) >> 2;
    uint32_t cpAo[2];
    const __half* srcA[2];
#pragma unroll
    for (int i = 0; i < 2; i++) {
        cpAo[i] = (uint32_t)(cpr[i] * 64 + (((cp_c0 ^ ((cpr[i] >> 1) & 3))) << 4));
        srcA[i] = gA + (size_t)cpr[i] * DDIM + cp_c0 * 8;
    }
    uint32_t cpBo[4];
    const __half* srcB[4];
#pragma unroll
    for (int i = 0; i < 4; i++) {
        int r = (tid + i * NTHREADS) >> 2;
        cpBo[i] = (uint32_t)(r * 64 + (((cp_c0 ^ ((r >> 1) & 3))) << 4));
        srcB[i] = gB + (size_t)r * DDIM + cp_c0 * 8;
    }

    // per-lane ldmatrix offsets (stage-relative); kf selects k16 half
    uint32_t aOff[2][4], bOff[2][4];
    {
        int rowW = wm * 64 + (m8 & 1) * 8 + r8;
        int sxa = (rowW >> 1) & 3;
#pragma unroll
        for (int kf = 0; kf < 2; kf++)
#pragma unroll
            for (int mi = 0; mi < 4; mi++)
                aOff[kf][mi] = (uint32_t)((rowW + mi * 16) * 64 +
                               (((kf * 2 + (m8 >> 1)) ^ sxa) << 4));
        int nW = wn * 64 + (m8 >> 1) * 8 + r8;
        int sxb = (nW >> 1) & 3;
#pragma unroll
        for (int kf = 0; kf < 2; kf++)
#pragma unroll
            for (int p = 0; p < 4; p++)
                bOff[kf][p] = (uint32_t)(A_STAGE_BYTES + (nW + p * 16) * 64 +
                              (((kf * 2 + (m8 & 1)) ^ sxb) << 4));
    }

    // f16x2 accumulators: [mi][n8][row-half] = 64 regs
    uint32_t acc[4][8][2];
#pragma unroll
    for (int mi = 0; mi < 4; mi++)
#pragma unroll
        for (int ni = 0; ni < 8; ni++) { acc[mi][ni][0] = 0u; acc[mi][ni][1] = 0u; }

    auto loadStage = [&](int st, int kt) {
        const uint32_t base = sbase + st * STAGE_BYTES;
        const int go = kt * BK;
#pragma unroll
        for (int i = 0; i < 2; i++) cp16(base + cpAo[i], srcA[i] + go);
#pragma unroll
        for (int i = 0; i < 4; i++)
            cp16(base + A_STAGE_BYTES + cpBo[i], srcB[i] + go);
        asm volatile("cp.async.commit_group;");
    };

    loadStage(0, 0);
    loadStage(1, 1);

#pragma unroll
    for (int kt = 0; kt < KT; kt++) {
        if (kt < KT - 1) cp_wait<1>(); else cp_wait<0>();
        __syncthreads();   // stage (kt+2)%3 slot fully consumed by all warps
        if (kt + 2 < KT) loadStage((kt + 2) % 3, kt + 2);

        const uint32_t stg = sbase + (kt % 3) * STAGE_BYTES;

#pragma unroll
        for (int kf = 0; kf < 2; kf++) {
            uint32_t b[4][4];
#pragma unroll
            for (int p = 0; p < 4; p++)
                LDSM4(b[p][0], b[p][1], b[p][2], b[p][3], stg + bOff[kf][p]);
#pragma unroll
            for (int mi = 0; mi < 4; mi++) {
                uint32_t a[4];
                LDSM4(a[0], a[1], a[2], a[3], stg + aOff[kf][mi]);
#pragma unroll
                for (int p = 0; p < 4; p++) {
                    mma_f16acc(acc[mi][2 * p],     a, b[p][0], b[p][1]);
                    mma_f16acc(acc[mi][2 * p + 1], a, b[p][2], b[p][3]);
                }
            }
        }
    }

    // ---- epilogue pass 1: d = z2 - 2*dot + p2 (f32), pack back to f16x2,
    //      track per-row min ---------------------------------------------------
#pragma unroll
    for (int mi = 0; mi < 4; mi++) {
#pragma unroll
        for (int h = 0; h < 2; h++) {
            int lrow = wm * 64 + mi * 16 + crow + h * 8;
            float z2v = g_z2[rowBase + lrow];
            float tmin = 3.4e38f;
#pragma unroll
            for (int ni = 0; ni < 8; ni++) {
                int gcol = colBase + wn * 64 + ni * 8 + 2 * qc;
                float2 dv = __half22float2(
                    *reinterpret_cast<__half2*>(&acc[mi][ni][h]));
                float d0 = (z2v - 2.0f * dv.x) + __ldg(&g_p2[gcol]);
                float d1 = (z2v - 2.0f * dv.y) + __ldg(&g_p2[gcol + 1]);
                tmin = fminf(tmin, fminf(d0, d1));
                // store distances back (f16 rounding <=0.25 << margin 16)
                acc[mi][ni][h] = pack2_h(d0, d1);
            }
            atomicMin(&srow[lrow], __float_as_uint(tmin));
        }
    }
    __syncthreads();

    if (tid < BM) atomicMin(&g_best[rowBase + tid], srow[tid]);

    // ---- epilogue pass 2: append candidates within margin -------------------
#pragma unroll
    for (int mi = 0; mi < 4; mi++) {
#pragma unroll
        for (int h = 0; h < 2; h++) {
            int lrow = wm * 64 + mi * 16 + crow + h * 8;
            int grow = rowBase + lrow;
            float gb = fminf(__uint_as_float(g_best[grow]),
                             __uint_as_float(srow[lrow]));
            float thr = gb + COARSE_THR;
#pragma unroll
            for (int ni = 0; ni < 8; ni++) {
                int gcol = colBase + wn * 64 + ni * 8 + 2 * qc;
                float2 dv = __half22float2(
                    *reinterpret_cast<__half2*>(&acc[mi][ni][h]));
#pragma unroll
                for (int e = 0; e < 2; e++) {
                    float d = (e == 0) ? dv.x : dv.y;
                    if (d < thr) {
                        int slot = atomicAdd(&g_ccnt[grow], 1);
                        if (slot < CAND_CAP)
                            g_cidx[(size_t)grow * CAND_CAP + slot] = gcol + e;
                    }
                }
            }
        }
    }
}

// ---------------- exact refinement + output ---------------------------------
__global__ void refine_kernel(const float* __restrict__ z,
                              const float* __restrict__ proto, int Mtot,
                              float* __restrict__ outW,
                              float* __restrict__ outIdxF,
                              int* __restrict__ outIdxI) {
    int warp = (blockIdx.x * blockDim.x + threadIdx.x) >> 5;
    int lane = threadIdx.x & 31;
    const int row = warp;
    const float z2 = g_z2[row];

    float4 zr[4];
#pragma unroll
    for (int i = 0; i < 4; i++)
        zr[i] = reinterpret_cast<const float4*>(z + (size_t)row * DDIM)[i * 32 + lane];

    int cnt = g_ccnt[row];
    float bestD = 3.4e38f;
    int bestI = 0;

    if (cnt <= CAND_CAP) {
        for (int k = 0; k < cnt; k++) {
            int c = g_cidx[(size_t)row * CAND_CAP + k];
            const float4* pr = reinterpret_cast<const float4*>(proto + (size_t)c * DDIM);
            float dot = 0.f;
#pragma unroll
            for (int i = 0; i < 4; i++) {
                float4 pv = pr[i * 32 + lane];
                dot += zr[i].x * pv.x + zr[i].y * pv.y + zr[i].z * pv.z + zr[i].w * pv.w;
            }
#pragma unroll
            for (int o = 16; o; o >>= 1) dot += __shfl_xor_sync(0xffffffffu, dot, o);
            float d = (z2 - 2.0f * dot) + __ldg(&g_p2[c]);
            if (d < bestD || (d == bestD && c < bestI)) { bestD = d; bestI = c; }
        }
    } else {
        for (int c = 0; c < Mtot; c++) {
            const float4* pr = reinterpret_cast<const float4*>(proto + (size_t)c * DDIM);
            float dot = 0.f;
#pragma unroll
            for (int i = 0; i < 4; i++) {
                float4 pv = pr[i * 32 + lane];
                dot += zr[i].x * pv.x + zr[i].y * pv.y + zr[i].z * pv.z + zr[i].w * pv.w;
            }
#pragma unroll
            for (int o = 16; o; o >>= 1) dot += __shfl_xor_sync(0xffffffffu, dot, o);
            float d = (z2 - 2.0f * dot) + __ldg(&g_p2[c]);
            if (d < bestD) { bestD = d; bestI = c; }
        }
    }

    if (lane == 0) {
        if (outIdxF) outIdxF[row] = (float)bestI;
        if (outIdxI) outIdxI[row] = bestI;
    }
    if (outW) {
        const float4* pr = reinterpret_cast<const float4*>(proto + (size_t)bestI * DDIM);
        float4* ow = reinterpret_cast<float4*>(outW + (size_t)row * DDIM);
#pragma unroll
        for (int i = 0; i < 4; i++) ow[i * 32 + lane] = pr[i * 32 + lane];
    }
}

// ---------------------------------------------------------------------------
extern "C" void kernel_launch(void* const* d_in, const int* in_sizes, int n_in,
                              void* d_out, int out_size) {
    const float* z = (const float*)d_in[0];
    const float* p = (const float*)d_in[1];
    int N = in_sizes[0] / DDIM;
    int M = in_sizes[1] / DDIM;

    float* p2; float* z2; __half* zh; __half* ph;
    cudaGetSymbolAddress((void**)&p2, g_p2);
    cudaGetSymbolAddress((void**)&z2, g_z2);
    cudaGetSymbolAddress((void**)&zh, g_zh);
    cudaGetSymbolAddress((void**)&ph, g_ph);

    zero_kernel<<<(N + 255) / 256, 256>>>(N);
    sqcvt_kernel<<<(M * 32 + 255) / 256, 256>>>(p, p2, ph, M);
    sqcvt_kernel<<<(N * 32 + 255) / 256, 256>>>(z, z2, zh, N);

    cudaFuncSetAttribute(som_mma_kernel,
                         cudaFuncAttributeMaxDynamicSharedMemorySize, SMEM_BYTES);
    dim3 grid(N / BM, M / BN);   // x = row tiles (fast), y = col tiles
    som_mma_kernel<<<grid, NTHREADS, SMEM_BYTES>>>();

    float* outW = nullptr;
    float* outIdxF = nullptr;
    int* outIdxI = nullptr;
    long long nd = (long long)N * DDIM;
    if ((long long)out_size >= nd) {
        outW = (float*)d_out;
        if ((long long)out_size >= nd + N) outIdxF = (float*)d_out + nd;
    } else if (out_size == N) {
        outIdxI = (int*)d_out;
    }

    refine_kernel<<<(N * 32) / 256, 256>>>(z, p, M, outW, outIdxF, outIdxI);
}